// round 1
// baseline (speedup 1.0000x reference)
#include <cuda_runtime.h>
#include <cuda_fp16.h>

// GraphMaxPooling: out[b,i,k] = sum_c max_j( adj[b,c,i,j] * x[b,j,k] )
// B=64, C=4, N=128, K=64. adj entries are exactly 0.0f or 1.0f.
//
// Strategy: adj rows -> 128-bit masks (ballot). x staged in SMEM as half2.
// One warp per (b,i) row; lane owns 2 k-values (half2). Per j: one LDS.32
// shared by all 4 channels, then per channel a predicated __hmax2.
// Zero-products handled exactly by a final max(acc, 0) when mask != all-ones.

#define GB 64
#define GC 4
#define GN 128
#define GK 64

__global__ __launch_bounds__(256, 4)
void GraphMaxPooling_82815559402085_kernel(const float* __restrict__ x,
                                           const float* __restrict__ adj,
                                           float* __restrict__ out) {
    // 16 blocks per b, 8 rows per block, 1 warp per row.
    const int b       = blockIdx.x >> 4;
    const int rowBase = (blockIdx.x & 15) << 3;
    const int tid     = threadIdx.x;
    const int lane    = tid & 31;
    const int warp    = tid >> 5;
    const int i       = rowBase + warp;

    // x[b] as half2: xs[j][k2], 128 rows x 32 half2 = 16 KB.
    __shared__ __half2 xs[GN][GK / 2];

    // ---- Stage x[b] (8192 floats) into SMEM as half2, float4-vectorized ----
    {
        const float4* xg = (const float4*)(x + (size_t)b * GN * GK);
        #pragma unroll
        for (int it = 0; it < 8; ++it) {
            int f4 = tid + 256 * it;           // 0..2047
            float4 v = xg[f4];
            int e = f4 << 2;                   // element index, multiple of 4
            int j = e >> 6;                    // /64
            int k2 = (e & 63) >> 1;            // half2 column
            xs[j][k2]     = __floats2half2_rn(v.x, v.y);
            xs[j][k2 + 1] = __floats2half2_rn(v.z, v.w);
        }
    }
    __syncthreads();

    // ---- Build 128-bit adjacency masks for this row, per channel ----
    unsigned m[GC][4];
    #pragma unroll
    for (int c = 0; c < GC; ++c) {
        const float* arow = adj + (((size_t)b * GC + c) * GN + i) * GN;
        #pragma unroll
        for (int q = 0; q < 4; ++q) {
            float a = arow[q * 32 + lane];
            m[c][q] = __ballot_sync(0xffffffffu, a != 0.0f);
        }
    }

    // ---- Main loop: predicated packed max ----
    const __half2 ninf = __half2half2(__ushort_as_half((unsigned short)0xFC00)); // -inf
    __half2 acc0 = ninf, acc1 = ninf, acc2 = ninf, acc3 = ninf;

    #pragma unroll
    for (int q = 0; q < 4; ++q) {
        const unsigned m0 = m[0][q], m1 = m[1][q], m2 = m[2][q], m3 = m[3][q];
        #pragma unroll
        for (int jj = 0; jj < 32; ++jj) {
            const unsigned bit = 1u << jj;
            const __half2 xv = xs[q * 32 + jj][lane];
            if (m0 & bit) acc0 = __hmax2(acc0, xv);
            if (m1 & bit) acc1 = __hmax2(acc1, xv);
            if (m2 & bit) acc2 = __hmax2(acc2, xv);
            if (m3 & bit) acc3 = __hmax2(acc3, xv);
        }
    }

    // ---- Zero-term fixup (exact) + fp32 channel sum ----
    const __half2 zero2 = __float2half2_rn(0.0f);
    float sx = 0.0f, sy = 0.0f;
    {
        unsigned a0 = m[0][0] & m[0][1] & m[0][2] & m[0][3];
        if (a0 != 0xffffffffu) acc0 = __hmax2(acc0, zero2);
        float2 f = __half22float2(acc0); sx += f.x; sy += f.y;
    }
    {
        unsigned a1 = m[1][0] & m[1][1] & m[1][2] & m[1][3];
        if (a1 != 0xffffffffu) acc1 = __hmax2(acc1, zero2);
        float2 f = __half22float2(acc1); sx += f.x; sy += f.y;
    }
    {
        unsigned a2 = m[2][0] & m[2][1] & m[2][2] & m[2][3];
        if (a2 != 0xffffffffu) acc2 = __hmax2(acc2, zero2);
        float2 f = __half22float2(acc2); sx += f.x; sy += f.y;
    }
    {
        unsigned a3 = m[3][0] & m[3][1] & m[3][2] & m[3][3];
        if (a3 != 0xffffffffu) acc3 = __hmax2(acc3, zero2);
        float2 f = __half22float2(acc3); sx += f.x; sy += f.y;
    }

    // ---- Store: lane writes float2 at out[b,i,2*lane] ----
    float2* o2 = (float2*)(out + ((size_t)b * GN + i) * GK);
    o2[lane] = make_float2(sx, sy);
}

extern "C" void kernel_launch(void* const* d_in, const int* in_sizes, int n_in,
                              void* d_out, int out_size) {
    const float* x   = (const float*)d_in[0];   // (B, N, K) float32
    const float* adj = (const float*)d_in[1];   // (B, C, N, N) float32
    float* out       = (float*)d_out;           // (B, N, K) float32
    (void)in_sizes; (void)n_in; (void)out_size;

    GraphMaxPooling_82815559402085_kernel<<<GB * 16, 256>>>(x, adj, out);
}

// round 2
// speedup vs baseline: 1.2622x; 1.2622x over previous
#include <cuda_runtime.h>
#include <cuda_fp16.h>

// GraphMaxPooling: out[b,i,k] = sum_c max_j( adj[b,c,i,j] * x[b,j,k] )
// B=64, C=4, N=128, K=64. adj entries are exactly 0.0f or 1.0f.
//
// R1 strategy: balance fma/alu pipes. Literal masked product via HMUL2 (fma
// pipe) feeding HMNMX2 (alu pipe). adj staged as half2 j-pairs (broadcast via
// .H0_H0/.H1_H1 operand selectors). x staged transposed [k2][j] with stride
// 132 -> conflict-free LDS.128 of 8 j's per lane. No masks, no predicates,
// no zero-fixup (zero products participate in the max naturally).

#define GB 64
#define GC 4
#define GN 128
#define GK 64
#define XS_STRIDE 132   // half2 units: 16B-aligned (132*4=528), 132%32==4 -> conflict-free LDS.128

__global__ __launch_bounds__(256, 5)
void GraphMaxPooling_82815559402085_kernel(const float* __restrict__ x,
                                           const float* __restrict__ adj,
                                           float* __restrict__ out) {
    // 16 blocks per b, 8 rows per block, 1 warp per row.
    const int b       = blockIdx.x >> 4;
    const int rowBase = (blockIdx.x & 15) << 3;
    const int tid     = threadIdx.x;
    const int lane    = tid & 31;
    const int warp    = tid >> 5;

    __shared__ __align__(16) __half2 xs[GK / 2][XS_STRIDE];  // [k2][j], ~16.9 KB
    __shared__ __align__(16) __half2 as_[8][GC][GN / 2];     // [warp][c][jpair], 8 KB

    // ---- Stage x[b] (128 x 64 fp32) transposed into xs[k2][j] as half2 ----
    {
        const float4* xg = (const float4*)(x + (size_t)b * GN * GK);
        #pragma unroll
        for (int t = 0; t < 8; ++t) {
            int f4 = tid + 256 * t;            // 0..2047
            float4 v = xg[f4];
            int e  = f4 << 2;                  // element index
            int j  = e >> 6;                   // row (j)
            int k2 = (e & 63) >> 1;            // half2 column
            xs[k2][j]     = __floats2half2_rn(v.x, v.y);
            xs[k2 + 1][j] = __floats2half2_rn(v.z, v.w);
        }
    }

    // ---- Stage adj rows (8 i's x 4 c x 128 j) as half2 j-pairs ----
    #pragma unroll
    for (int c = 0; c < GC; ++c) {
        // 8 consecutive rows (rowBase..rowBase+7) for this (b,c): 1024 floats.
        const float4* ag = (const float4*)(adj + (((size_t)b * GC + c) * GN + rowBase) * GN);
        float4 v = ag[tid];                    // 256 float4 per chunk
        int w  = tid >> 5;                     // dest warp/row
        int j2 = (tid & 31) << 1;              // half2-pair index (j/2)
        as_[w][c][j2]     = __floats2half2_rn(v.x, v.y);
        as_[w][c][j2 + 1] = __floats2half2_rn(v.z, v.w);
    }
    __syncthreads();

    const __half2* xrow = xs[lane];
    const __half2 NINF = __half2half2(__ushort_as_half((unsigned short)0xFC00));
    __half2 acc0 = NINF, acc1 = NINF, acc2 = NINF, acc3 = NINF;

    #pragma unroll 4
    for (int jb = 0; jb < GN; jb += 8) {
        // 8 x-values for my k-pair: two 128-bit shared loads.
        uint4 xa = *(const uint4*)(xrow + jb);
        uint4 xb = *(const uint4*)(xrow + jb + 4);
        __half2 xv0 = *(__half2*)&xa.x, xv1 = *(__half2*)&xa.y;
        __half2 xv2 = *(__half2*)&xa.z, xv3 = *(__half2*)&xa.w;
        __half2 xv4 = *(__half2*)&xb.x, xv5 = *(__half2*)&xb.y;
        __half2 xv6 = *(__half2*)&xb.z, xv7 = *(__half2*)&xb.w;

        #pragma unroll
        for (int c = 0; c < GC; ++c) {
            // 4 adjacency j-pairs for (row, c): one 128-bit broadcast load.
            uint4 av = *(const uint4*)(&as_[warp][c][jb >> 1]);
            __half2 a0 = *(__half2*)&av.x, a1 = *(__half2*)&av.y;
            __half2 a2 = *(__half2*)&av.z, a3 = *(__half2*)&av.w;

            __half2 p0 = __hmul2(xv0, __low2half2(a0));
            __half2 p1 = __hmul2(xv1, __high2half2(a0));
            __half2 p2 = __hmul2(xv2, __low2half2(a1));
            __half2 p3 = __hmul2(xv3, __high2half2(a1));
            __half2 p4 = __hmul2(xv4, __low2half2(a2));
            __half2 p5 = __hmul2(xv5, __high2half2(a2));
            __half2 p6 = __hmul2(xv6, __low2half2(a3));
            __half2 p7 = __hmul2(xv7, __high2half2(a3));

            __half2 m01 = __hmax2(p0, p1);
            __half2 m23 = __hmax2(p2, p3);
            __half2 m45 = __hmax2(p4, p5);
            __half2 m67 = __hmax2(p6, p7);
            __half2 m03 = __hmax2(m01, m23);
            __half2 m47 = __hmax2(m45, m67);
            __half2 m   = __hmax2(m03, m47);

            if (c == 0) acc0 = __hmax2(acc0, m);
            else if (c == 1) acc1 = __hmax2(acc1, m);
            else if (c == 2) acc2 = __hmax2(acc2, m);
            else acc3 = __hmax2(acc3, m);
        }
    }

    // ---- fp32 channel sum + store (lane owns k = 2*lane, 2*lane+1) ----
    float2 f0 = __half22float2(acc0);
    float2 f1 = __half22float2(acc1);
    float2 f2 = __half22float2(acc2);
    float2 f3 = __half22float2(acc3);
    float sx = (f0.x + f1.x) + (f2.x + f3.x);
    float sy = (f0.y + f1.y) + (f2.y + f3.y);

    const int i = rowBase + warp;
    float2* o2 = (float2*)(out + ((size_t)b * GN + i) * GK);
    o2[lane] = make_float2(sx, sy);
}

extern "C" void kernel_launch(void* const* d_in, const int* in_sizes, int n_in,
                              void* d_out, int out_size) {
    const float* x   = (const float*)d_in[0];   // (B, N, K) float32
    const float* adj = (const float*)d_in[1];   // (B, C, N, N) float32
    float* out       = (float*)d_out;           // (B, N, K) float32
    (void)in_sizes; (void)n_in; (void)out_size;

    GraphMaxPooling_82815559402085_kernel<<<GB * 16, 256>>>(x, adj, out);
}